// round 3
// baseline (speedup 1.0000x reference)
#include <cuda_runtime.h>

#define BHN   128          // B*H
#define SEQ   4096
#define DIM   64
#define SPLIT 16
#define ROWS_PER_SPLIT (SEQ / SPLIT)   // 256
#define CHUNK 32
#define EPSF  1e-6f

typedef unsigned long long u64;

// Scratch (device globals: allocation-free per harness rules)
__device__ float g_ctx_partial[BHN * SPLIT * DIM * DIM]; // 32 MB
__device__ float g_cs_partial [BHN * SPLIT * DIM];
__device__ u64   g_ctxd       [BHN * DIM * DIM];         // 4 MB, DUPLICATED pairs (c,c)

// ---- packed fp32x2 helpers ----
__device__ __forceinline__ void fma2(u64 &d, u64 a, u64 b) {
    asm("fma.rn.f32x2 %0, %1, %2, %0;" : "+l"(d) : "l"(a), "l"(b));
}
__device__ __forceinline__ float2 unpack2(u64 a) {
    float2 f; asm("mov.b64 {%0, %1}, %2;" : "=f"(f.x), "=f"(f.y) : "l"(a)); return f;
}

// ============================================================================
// Kernel 1: partial ctx[d][e] = sum_n e^{K[n][d]} * V[n][e] over an n-split.
// 128 threads. Thread tile: 8 d (as 4 natural f32x2 pairs) x 4 e (dup'd in smem).
//   tx = tid&15 -> e cols 4tx..4tx+3 ;  ty = tid>>4 -> d rows 8ty..8ty+7.
// Inner step: 4 LDS.128 + 16 FFMA2, zero MOVs.
// ============================================================================
__global__ __launch_bounds__(128, 5)
void ctx_kernel(const float* __restrict__ kp, const float* __restrict__ vp)
{
    __shared__ __align__(16) float s_ek[CHUNK][DIM]; //  8 KB  e^K natural [n][d]
    __shared__ __align__(16) u64   s_vd[CHUNK][DIM]; // 16 KB  V duplicated [n][e]
    __shared__ __align__(16) float s_red[8][DIM];    //  2 KB  colsum reduction

    const int tid = threadIdx.x;
    const int tx = tid & 15, ty = tid >> 4;
    const int dcol = tid & 15;                       // staging d-group
    const int split = blockIdx.x, bh = blockIdx.y;
    const size_t base = ((size_t)bh * SEQ + (size_t)split * ROWS_PER_SPLIT) * DIM;

    u64 acc[4][4];                                   // [d-pair][e]
#pragma unroll
    for (int i = 0; i < 4; i++)
#pragma unroll
        for (int j = 0; j < 4; j++) acc[i][j] = 0ull;
    float4 cs = make_float4(0.f, 0.f, 0.f, 0.f);     // colsum for d = 4*dcol..+3

    for (int ch = 0; ch < ROWS_PER_SPLIT / CHUNK; ch++) {
        // ---- stage chunk: e^K natural, V duplicated ----
#pragma unroll
        for (int r = 0; r < 4; r++) {
            const int idx = r * 128 + tid;           // 0..511 float4s
            const int nl  = idx >> 4;                // 0..31
            const size_t goff = base + (size_t)(ch * CHUNK + nl) * DIM + 4 * dcol;
            const float4 kk = *(const float4*)(kp + goff);
            const float e0 = __expf(kk.x), e1 = __expf(kk.y),
                        e2 = __expf(kk.z), e3 = __expf(kk.w);
            *(float4*)&s_ek[nl][4 * dcol] = make_float4(e0, e1, e2, e3);
            cs.x += e0; cs.y += e1; cs.z += e2; cs.w += e3;
            const float4 vv = *(const float4*)(vp + goff);
            float4* vd = (float4*)&s_vd[nl][4 * dcol];
            vd[0] = make_float4(vv.x, vv.x, vv.y, vv.y);
            vd[1] = make_float4(vv.z, vv.z, vv.w, vv.w);
        }
        __syncthreads();

        // ---- rank-1 updates ----
#pragma unroll 8
        for (int n = 0; n < CHUNK; n++) {
            const ulonglong2 ea = *(const ulonglong2*)&s_ek[n][8 * ty];     // (d0,d1),(d2,d3)
            const ulonglong2 eb = *(const ulonglong2*)&s_ek[n][8 * ty + 4]; // (d4,d5),(d6,d7)
            const ulonglong2 va = *(const ulonglong2*)&s_vd[n][4 * tx];     // dup e0, e1
            const ulonglong2 vb = *(const ulonglong2*)&s_vd[n][4 * tx + 2]; // dup e2, e3
            fma2(acc[0][0], ea.x, va.x); fma2(acc[0][1], ea.x, va.y);
            fma2(acc[0][2], ea.x, vb.x); fma2(acc[0][3], ea.x, vb.y);
            fma2(acc[1][0], ea.y, va.x); fma2(acc[1][1], ea.y, va.y);
            fma2(acc[1][2], ea.y, vb.x); fma2(acc[1][3], ea.y, vb.y);
            fma2(acc[2][0], eb.x, va.x); fma2(acc[2][1], eb.x, va.y);
            fma2(acc[2][2], eb.x, vb.x); fma2(acc[2][3], eb.x, vb.y);
            fma2(acc[3][0], eb.y, va.x); fma2(acc[3][1], eb.y, va.y);
            fma2(acc[3][2], eb.y, vb.x); fma2(acc[3][3], eb.y, vb.y);
        }
        __syncthreads();
    }

    // ---- colsum partial ----
    *(float4*)&s_red[tid >> 4][4 * dcol] = cs;
    __syncthreads();
    const int pbase = bh * SPLIT + split;
    if (tid < DIM) {
        float s = 0.f;
#pragma unroll
        for (int y = 0; y < 8; y++) s += s_red[y][tid];
        g_cs_partial[pbase * DIM + tid] = s;
    }

    // ---- context partial: rows d = 8ty+2i(+1), cols 4tx..4tx+3 ----
    float* cp = g_ctx_partial + (size_t)pbase * DIM * DIM;
#pragma unroll
    for (int i = 0; i < 4; i++) {
        const float2 u0 = unpack2(acc[i][0]);
        const float2 u1 = unpack2(acc[i][1]);
        const float2 u2 = unpack2(acc[i][2]);
        const float2 u3 = unpack2(acc[i][3]);
        const int r0 = 8 * ty + 2 * i;
        *(float4*)(cp + (size_t)r0 * DIM + 4 * tx) =
            make_float4(u0.x, u1.x, u2.x, u3.x);
        *(float4*)(cp + (size_t)(r0 + 1) * DIM + 4 * tx) =
            make_float4(u0.y, u1.y, u2.y, u3.y);
    }
}

// ============================================================================
// Kernel 2: reduce split partials, normalize, emit DUPLICATED context pairs.
// ============================================================================
__global__ __launch_bounds__(256)
void reduce_kernel()
{
    const int bh = blockIdx.x, tid = threadIdx.x;
    __shared__ float inv[DIM];
    if (tid < DIM) {
        float s = 0.f;
#pragma unroll
        for (int sp = 0; sp < SPLIT; sp++)
            s += g_cs_partial[(bh * SPLIT + sp) * DIM + tid];
        inv[tid] = 1.0f / (s * (1.0f + EPSF));
    }
    __syncthreads();
#pragma unroll
    for (int r = 0; r < 4; r++) {
        const int i4 = r * 256 + tid;            // float4 index over [d][e] (1024)
        float4 s = make_float4(0.f, 0.f, 0.f, 0.f);
#pragma unroll
        for (int sp = 0; sp < SPLIT; sp++) {
            const float4 p = *(const float4*)(g_ctx_partial +
                (size_t)(bh * SPLIT + sp) * DIM * DIM + 4 * i4);
            s.x += p.x; s.y += p.y; s.z += p.z; s.w += p.w;
        }
        const float iv = inv[i4 >> 4];           // d = (4*i4)/64
        s.x *= iv; s.y *= iv; s.z *= iv; s.w *= iv;
        const int d = i4 >> 4, e0 = 4 * (i4 & 15);
        float4* dst = (float4*)(g_ctxd + (size_t)bh * DIM * DIM + d * DIM + e0);
        dst[0] = make_float4(s.x, s.x, s.y, s.y);
        dst[1] = make_float4(s.z, s.z, s.w, s.w);
    }
}

// ============================================================================
// Kernel 3: out = rowsoftmax(Q) @ ctx.  128 threads / 128 rows per block.
// Thread tile: 8 n (4 natural pairs from p^T) x 8 e (dup'd ctx).
//   tx = tid&7 -> e cols 8tx..8tx+7 ;  ty = tid>>3 -> n rows 8ty..8ty+7.
// Inner step: 6 LDS.128 + 32 FFMA2.
// ============================================================================
#define ONB 128   // n-rows per block

__global__ __launch_bounds__(128, 3)
void out_kernel(const float* __restrict__ qp, float* __restrict__ outp)
{
    __shared__ __align__(16) float s_pT[DIM][ONB];  // 32 KB  p^T [d][n]
    __shared__ __align__(16) u64   s_cd[DIM][DIM];  // 32 KB  dup ctx [d][e]

    const int tid = threadIdx.x;
    const int tx = tid & 7, ty = tid >> 3;
    const int nb = blockIdx.x, bh = blockIdx.y;

    // stage duplicated ctx (plain copy, already dup'd by reduce_kernel)
    {
        const float4* src = (const float4*)(g_ctxd + (size_t)bh * DIM * DIM);
        float4* dst = (float4*)s_cd;
#pragma unroll
        for (int r = 0; r < 16; r++) {
            const int i = r * 128 + tid;
            dst[i] = src[i];
        }
    }

    // row softmax of q: 1 thread per row, fully in registers
    {
        const float* qr = qp + ((size_t)bh * SEQ + (size_t)nb * ONB + tid) * DIM;
        float e[DIM];
#pragma unroll
        for (int i = 0; i < 16; i++) {
            const float4 a = *(const float4*)(qr + 4 * i);
            e[4*i] = a.x; e[4*i+1] = a.y; e[4*i+2] = a.z; e[4*i+3] = a.w;
        }
        float m = e[0];
#pragma unroll
        for (int i = 1; i < DIM; i++) m = fmaxf(m, e[i]);
        float s = 0.f;
#pragma unroll
        for (int i = 0; i < DIM; i++) { e[i] = __expf(e[i] - m); s += e[i]; }
        const float rinv = 1.0f / s;
#pragma unroll
        for (int d = 0; d < DIM; d++) s_pT[d][tid] = e[d] * rinv;
    }
    __syncthreads();

    // GEMM: out[n][e] = sum_d p[n][d] * ctx[d][e]
    u64 acc[4][8];                                   // [n-pair][e]
#pragma unroll
    for (int i = 0; i < 4; i++)
#pragma unroll
        for (int j = 0; j < 8; j++) acc[i][j] = 0ull;

#pragma unroll 8
    for (int d = 0; d < DIM; d++) {
        const ulonglong2 pa = *(const ulonglong2*)&s_pT[d][8 * ty];     // (n0,n1),(n2,n3)
        const ulonglong2 pb = *(const ulonglong2*)&s_pT[d][8 * ty + 4]; // (n4,n5),(n6,n7)
        const ulonglong2 c0 = *(const ulonglong2*)&s_cd[d][8 * tx];     // dup e0,e1
        const ulonglong2 c1 = *(const ulonglong2*)&s_cd[d][8 * tx + 2];
        const ulonglong2 c2 = *(const ulonglong2*)&s_cd[d][8 * tx + 4];
        const ulonglong2 c3 = *(const ulonglong2*)&s_cd[d][8 * tx + 6];
        fma2(acc[0][0], pa.x, c0.x); fma2(acc[0][1], pa.x, c0.y);
        fma2(acc[0][2], pa.x, c1.x); fma2(acc[0][3], pa.x, c1.y);
        fma2(acc[0][4], pa.x, c2.x); fma2(acc[0][5], pa.x, c2.y);
        fma2(acc[0][6], pa.x, c3.x); fma2(acc[0][7], pa.x, c3.y);
        fma2(acc[1][0], pa.y, c0.x); fma2(acc[1][1], pa.y, c0.y);
        fma2(acc[1][2], pa.y, c1.x); fma2(acc[1][3], pa.y, c1.y);
        fma2(acc[1][4], pa.y, c2.x); fma2(acc[1][5], pa.y, c2.y);
        fma2(acc[1][6], pa.y, c3.x); fma2(acc[1][7], pa.y, c3.y);
        fma2(acc[2][0], pb.x, c0.x); fma2(acc[2][1], pb.x, c0.y);
        fma2(acc[2][2], pb.x, c1.x); fma2(acc[2][3], pb.x, c1.y);
        fma2(acc[2][4], pb.x, c2.x); fma2(acc[2][5], pb.x, c2.y);
        fma2(acc[2][6], pb.x, c3.x); fma2(acc[2][7], pb.x, c3.y);
        fma2(acc[3][0], pb.y, c0.x); fma2(acc[3][1], pb.y, c0.y);
        fma2(acc[3][2], pb.y, c1.x); fma2(acc[3][3], pb.y, c1.y);
        fma2(acc[3][4], pb.y, c2.x); fma2(acc[3][5], pb.y, c2.y);
        fma2(acc[3][6], pb.y, c3.x); fma2(acc[3][7], pb.y, c3.y);
    }

    // epilogue: acc[p][j] = (out[8ty+2p][8tx+j], out[8ty+2p+1][8tx+j])
    const size_t obase = ((size_t)bh * SEQ + (size_t)nb * ONB) * DIM;
#pragma unroll
    for (int p = 0; p < 4; p++) {
        const float2 u0 = unpack2(acc[p][0]);
        const float2 u1 = unpack2(acc[p][1]);
        const float2 u2 = unpack2(acc[p][2]);
        const float2 u3 = unpack2(acc[p][3]);
        const float2 u4 = unpack2(acc[p][4]);
        const float2 u5 = unpack2(acc[p][5]);
        const float2 u6 = unpack2(acc[p][6]);
        const float2 u7 = unpack2(acc[p][7]);
        const int r0 = 8 * ty + 2 * p;
        float* row0 = outp + obase + (size_t)r0 * DIM + 8 * tx;
        float* row1 = row0 + DIM;
        *(float4*)(row0)     = make_float4(u0.x, u1.x, u2.x, u3.x);
        *(float4*)(row0 + 4) = make_float4(u4.x, u5.x, u6.x, u7.x);
        *(float4*)(row1)     = make_float4(u0.y, u1.y, u2.y, u3.y);
        *(float4*)(row1 + 4) = make_float4(u4.y, u5.y, u6.y, u7.y);
    }
}

// ============================================================================
extern "C" void kernel_launch(void* const* d_in, const int* in_sizes, int n_in,
                              void* d_out, int out_size)
{
    const float* q = (const float*)d_in[0];
    const float* k = (const float*)d_in[1];
    const float* v = (const float*)d_in[2];
    float* out = (float*)d_out;

    ctx_kernel  <<<dim3(SPLIT, BHN), 128>>>(k, v);
    reduce_kernel<<<BHN, 256>>>();
    out_kernel  <<<dim3(SEQ / ONB, BHN), 128>>>(q, out);
}

// round 5
// speedup vs baseline: 1.7471x; 1.7471x over previous
#include <cuda_runtime.h>

#define BHN   128
#define SEQ   4096
#define DIM   64
#define SPLIT 16
#define RPS   (SEQ / SPLIT)   // 256
#define CHUNK 32
#define EPSF  1e-6f

typedef unsigned long long u64;

// Scratch (device globals: allocation-free per harness rules)
__device__ float g_ctx_partial[BHN * SPLIT * DIM * DIM]; // 33.5 MB
__device__ float g_cs_partial [BHN * SPLIT * DIM];
__device__ u64   g_ctxd      [BHN * DIM * DIM];          // 4 MB dup'd, interleaved

__device__ __forceinline__ void fma2(u64 &d, u64 a, u64 b) {
    asm("fma.rn.f32x2 %0, %1, %2, %0;" : "+l"(d) : "l"(a), "l"(b));
}
__device__ __forceinline__ float2 unpack2(u64 a) {
    float2 f; asm("mov.b64 {%0, %1}, %2;" : "=f"(f.x), "=f"(f.y) : "l"(a)); return f;
}

// ============================================================================
// Kernel 1: partial ctx[d][e] = sum_n e^{K[n][d]} * V[n][e] over an n-split.
// 128 threads (4 warps). Per-thread tile: 8 d x 4 e, acc pairs over d.
//  lane l: dg = l>>3 (4 groups), eg = l&7 (8 groups); warp w: dhalf=w&1, ehalf=w>>1.
//  d rows: 32*dhalf + 8*dg + 0..7 ; e cols: 32*ehalf + 4*eg + 0..3.
// smem: s_ek natural [n][d] (row 64 f32);
//       s_vd dup'd interleaved: e=32h+4eg+2p+t -> u64 idx n*64 + 32h + 16p + 2eg + t
//  => inner reads: 2 ek LDS.128 (conflict-free) + 2 vd LDS.128 (each one 128B line).
// ============================================================================
__global__ __launch_bounds__(128, 6)
void ctx_kernel(const float* __restrict__ kp, const float* __restrict__ vp)
{
    __shared__ __align__(16) float s_ek[CHUNK * DIM];  //  8 KB
    __shared__ __align__(16) u64   s_vd[CHUNK * DIM];  // 16 KB
    __shared__ __align__(16) float s_red[8 * DIM];     //  2 KB

    const int tid = threadIdx.x;
    const int w = tid >> 5, l = tid & 31;
    const int dg = l >> 3, eg = l & 7;
    const int dbase = 32 * (w & 1) + 8 * dg;           // word offset in ek row
    const int vbase = 32 * (w >> 1) + 2 * eg;          // u64 offset in vd row
    const int hh = tid >> 4, dcol = tid & 15;          // staging coords
    const int split = blockIdx.x, bh = blockIdx.y;
    const size_t base = ((size_t)bh * SEQ + (size_t)split * RPS) * DIM;

    // staging store offsets
    const int vsb = 32 * (dcol >> 3) + 2 * (dcol & 7); // u64 idx for v dup (p=0)

    u64 acc[4][4];                                     // [d-pair][e]
#pragma unroll
    for (int i = 0; i < 4; i++)
#pragma unroll
        for (int j = 0; j < 4; j++) acc[i][j] = 0ull;
    float4 cs = make_float4(0.f, 0.f, 0.f, 0.f);       // colsum for d=4dcol..+3

    for (int ch = 0; ch < RPS / CHUNK; ch++) {
        // ---- stage chunk ----
#pragma unroll
        for (int r = 0; r < 4; r++) {
            const int nl = 8 * r + hh;                 // 0..31
            const size_t goff = base + (size_t)(ch * CHUNK + nl) * DIM + 4 * dcol;
            const float4 kk = *(const float4*)(kp + goff);
            const float e0 = __expf(kk.x), e1 = __expf(kk.y),
                        e2 = __expf(kk.z), e3 = __expf(kk.w);
            cs.x += e0; cs.y += e1; cs.z += e2; cs.w += e3;
            *(float4*)&s_ek[nl * DIM + 4 * dcol] = make_float4(e0, e1, e2, e3);
            const float4 vv = *(const float4*)(vp + goff);
            u64* vrow = s_vd + nl * DIM + vsb;
            *(float4*)(vrow)      = make_float4(vv.x, vv.x, vv.y, vv.y); // p=0: e, e+1
            *(float4*)(vrow + 16) = make_float4(vv.z, vv.z, vv.w, vv.w); // p=1: e+2, e+3
        }
        __syncthreads();

        // ---- rank-1 updates: 4 LDS.128 + 16 FFMA2 per n ----
#pragma unroll 8
        for (int n = 0; n < CHUNK; n++) {
            const float* ekn = s_ek + n * DIM + dbase;
            const u64*   vdn = s_vd + n * DIM + vbase;
            const ulonglong2 eA = *(const ulonglong2*)(ekn);      // (d0,d1),(d2,d3)
            const ulonglong2 eB = *(const ulonglong2*)(ekn + 4);  // (d4,d5),(d6,d7)
            const ulonglong2 v0 = *(const ulonglong2*)(vdn);      // dup e0, e1
            const ulonglong2 v1 = *(const ulonglong2*)(vdn + 16); // dup e2, e3
            fma2(acc[0][0], eA.x, v0.x); fma2(acc[0][1], eA.x, v0.y);
            fma2(acc[0][2], eA.x, v1.x); fma2(acc[0][3], eA.x, v1.y);
            fma2(acc[1][0], eA.y, v0.x); fma2(acc[1][1], eA.y, v0.y);
            fma2(acc[1][2], eA.y, v1.x); fma2(acc[1][3], eA.y, v1.y);
            fma2(acc[2][0], eB.x, v0.x); fma2(acc[2][1], eB.x, v0.y);
            fma2(acc[2][2], eB.x, v1.x); fma2(acc[2][3], eB.x, v1.y);
            fma2(acc[3][0], eB.y, v0.x); fma2(acc[3][1], eB.y, v0.y);
            fma2(acc[3][2], eB.y, v1.x); fma2(acc[3][3], eB.y, v1.y);
        }
        __syncthreads();
    }

    // ---- colsum partial ----
    *(float4*)&s_red[hh * DIM + 4 * dcol] = cs;
    __syncthreads();
    const int pbase = bh * SPLIT + split;
    if (tid < DIM) {
        float s = 0.f;
#pragma unroll
        for (int y = 0; y < 8; y++) s += s_red[y * DIM + tid];
        g_cs_partial[pbase * DIM + tid] = s;
    }

    // ---- context partial (plain [d][e]) ----
    float* cp = g_ctx_partial + (size_t)pbase * DIM * DIM;
    const int ecol = 32 * (w >> 1) + 4 * eg;
#pragma unroll
    for (int p = 0; p < 4; p++) {
        const float2 u0 = unpack2(acc[p][0]);
        const float2 u1 = unpack2(acc[p][1]);
        const float2 u2 = unpack2(acc[p][2]);
        const float2 u3 = unpack2(acc[p][3]);
        const int r0 = dbase + 2 * p;
        *(float4*)(cp + (size_t)r0 * DIM + ecol) =
            make_float4(u0.x, u1.x, u2.x, u3.x);
        *(float4*)(cp + (size_t)(r0 + 1) * DIM + ecol) =
            make_float4(u0.y, u1.y, u2.y, u3.y);
    }
}

// ============================================================================
// Kernel 2: reduce split partials, normalize, emit dup'd ctx in out_kernel's
// interleaved layout: e = 8eg+2p+t  ->  u64 idx d*64 + 16p + 2eg + t.
// For a float4 at e0=4c:  idx0 = 32*(c&1) + 2*(c>>1)  (covers e0,e0+1),
//                         idx0+16 covers e0+2,e0+3.   (verified by example)
// ============================================================================
__global__ __launch_bounds__(256)
void reduce_kernel()
{
    const int bh = blockIdx.x, tid = threadIdx.x;
    __shared__ float inv[DIM];
    if (tid < DIM) {
        float s = 0.f;
#pragma unroll
        for (int sp = 0; sp < SPLIT; sp++)
            s += g_cs_partial[(bh * SPLIT + sp) * DIM + tid];
        inv[tid] = 1.0f / (s * (1.0f + EPSF));
    }
    __syncthreads();
#pragma unroll
    for (int r = 0; r < 4; r++) {
        const int i4 = r * 256 + tid;                // float4 index over [d][e]
        float4 s = make_float4(0.f, 0.f, 0.f, 0.f);
#pragma unroll
        for (int sp = 0; sp < SPLIT; sp++) {
            const float4 p = *(const float4*)(g_ctx_partial +
                (size_t)(bh * SPLIT + sp) * DIM * DIM + 4 * i4);
            s.x += p.x; s.y += p.y; s.z += p.z; s.w += p.w;
        }
        const float iv = inv[i4 >> 4];               // d
        s.x *= iv; s.y *= iv; s.z *= iv; s.w *= iv;
        const int d = i4 >> 4, c = i4 & 15;
        const int idx0 = 32 * (c & 1) + 2 * (c >> 1);
        u64* row = g_ctxd + (size_t)bh * DIM * DIM + d * DIM;
        *(float4*)(row + idx0)      = make_float4(s.x, s.x, s.y, s.y);
        *(float4*)(row + idx0 + 16) = make_float4(s.z, s.z, s.w, s.w);
    }
}

// ============================================================================
// Kernel 3: out = rowsoftmax(Q) @ ctx.  128 threads, 128 n-rows per block.
// Per-thread tile: 8 n x 8 e.  lane: ng = l>>3, eg = l&7; warp w -> n base 32w.
//  n rows: 32w + 8ng + 0..7 ; e cols: 8eg + 0..7.
// Inner per d: 2 pT LDS.128 (natural n-pairs) + 4 cd LDS.128 (dup'd interleaved,
// each one contiguous 128B line) + 32 FFMA2.
// ============================================================================
#define ONB 128

__global__ __launch_bounds__(128)
void out_kernel(const float* __restrict__ qp, float* __restrict__ outp)
{
    __shared__ __align__(16) float s_pT[DIM * ONB];  // 32 KB  p^T [d][n]
    __shared__ __align__(16) u64   s_cd[DIM * DIM];  // 32 KB  dup'd interleaved ctx

    const int tid = threadIdx.x;
    const int w = tid >> 5, l = tid & 31;
    const int ng = l >> 3, eg = l & 7;
    const int nbase = 32 * w + 8 * ng;
    const int nb = blockIdx.x, bh = blockIdx.y;

    // stage dup'd ctx (plain linear copy; layout already interleaved)
    {
        const float4* src = (const float4*)(g_ctxd + (size_t)bh * DIM * DIM);
        float4* dst = (float4*)s_cd;
#pragma unroll
        for (int r = 0; r < 16; r++) dst[r * 128 + tid] = src[r * 128 + tid];
    }

    // row softmax of q: 2 threads per row, 2 passes of 64 rows
#pragma unroll
    for (int pass = 0; pass < 2; pass++) {
        const int row = 64 * pass + (tid >> 1), part = tid & 1;
        const float* qr = qp + ((size_t)bh * SEQ + (size_t)nb * ONB + row) * DIM + part * 32;
        float e[32];
#pragma unroll
        for (int i = 0; i < 8; i++) {
            const float4 a = *(const float4*)(qr + 4 * i);
            e[4*i] = a.x; e[4*i+1] = a.y; e[4*i+2] = a.z; e[4*i+3] = a.w;
        }
        float m = e[0];
#pragma unroll
        for (int i = 1; i < 32; i++) m = fmaxf(m, e[i]);
        m = fmaxf(m, __shfl_xor_sync(0xffffffffu, m, 1));
        float s = 0.f;
#pragma unroll
        for (int i = 0; i < 32; i++) { e[i] = __expf(e[i] - m); s += e[i]; }
        s += __shfl_xor_sync(0xffffffffu, s, 1);
        const float rinv = 1.0f / s;
#pragma unroll
        for (int i = 0; i < 32; i++)
            s_pT[(32 * part + i) * ONB + row] = e[i] * rinv;
    }
    __syncthreads();

    // GEMM: out[n][e] = sum_d p[n][d] * ctx[d][e]
    u64 acc[4][8];                                   // [n-pair][e]
#pragma unroll
    for (int i = 0; i < 4; i++)
#pragma unroll
        for (int j = 0; j < 8; j++) acc[i][j] = 0ull;

#pragma unroll 8
    for (int d = 0; d < DIM; d++) {
        const float* pd = s_pT + d * ONB + nbase;
        const u64*   cd = s_cd + d * DIM + 2 * eg;
        const ulonglong2 pA = *(const ulonglong2*)(pd);       // (n0,n1),(n2,n3)
        const ulonglong2 pB = *(const ulonglong2*)(pd + 4);   // (n4,n5),(n6,n7)
        const ulonglong2 c0 = *(const ulonglong2*)(cd);       // dup e0, e1
        const ulonglong2 c1 = *(const ulonglong2*)(cd + 16);  // dup e2, e3
        const ulonglong2 c2 = *(const ulonglong2*)(cd + 32);  // dup e4, e5
        const ulonglong2 c3 = *(const ulonglong2*)(cd + 48);  // dup e6, e7
        fma2(acc[0][0], pA.x, c0.x); fma2(acc[0][1], pA.x, c0.y);
        fma2(acc[0][2], pA.x, c1.x); fma2(acc[0][3], pA.x, c1.y);
        fma2(acc[0][4], pA.x, c2.x); fma2(acc[0][5], pA.x, c2.y);
        fma2(acc[0][6], pA.x, c3.x); fma2(acc[0][7], pA.x, c3.y);
        fma2(acc[1][0], pA.y, c0.x); fma2(acc[1][1], pA.y, c0.y);
        fma2(acc[1][2], pA.y, c1.x); fma2(acc[1][3], pA.y, c1.y);
        fma2(acc[1][4], pA.y, c2.x); fma2(acc[1][5], pA.y, c2.y);
        fma2(acc[1][6], pA.y, c3.x); fma2(acc[1][7], pA.y, c3.y);
        fma2(acc[2][0], pB.x, c0.x); fma2(acc[2][1], pB.x, c0.y);
        fma2(acc[2][2], pB.x, c1.x); fma2(acc[2][3], pB.x, c1.y);
        fma2(acc[2][4], pB.x, c2.x); fma2(acc[2][5], pB.x, c2.y);
        fma2(acc[2][6], pB.x, c3.x); fma2(acc[2][7], pB.x, c3.y);
        fma2(acc[3][0], pB.y, c0.x); fma2(acc[3][1], pB.y, c0.y);
        fma2(acc[3][2], pB.y, c1.x); fma2(acc[3][3], pB.y, c1.y);
        fma2(acc[3][4], pB.y, c2.x); fma2(acc[3][5], pB.y, c2.y);
        fma2(acc[3][6], pB.y, c3.x); fma2(acc[3][7], pB.y, c3.y);
    }

    // epilogue: acc[p][k] = (out[nbase+2p][8eg+k], out[nbase+2p+1][8eg+k])
    const size_t obase = ((size_t)bh * SEQ + (size_t)nb * ONB) * DIM;
#pragma unroll
    for (int p = 0; p < 4; p++) {
        const float2 u0 = unpack2(acc[p][0]);
        const float2 u1 = unpack2(acc[p][1]);
        const float2 u2 = unpack2(acc[p][2]);
        const float2 u3 = unpack2(acc[p][3]);
        const float2 u4 = unpack2(acc[p][4]);
        const float2 u5 = unpack2(acc[p][5]);
        const float2 u6 = unpack2(acc[p][6]);
        const float2 u7 = unpack2(acc[p][7]);
        float* row0 = outp + obase + (size_t)(nbase + 2 * p) * DIM + 8 * eg;
        float* row1 = row0 + DIM;
        *(float4*)(row0)     = make_float4(u0.x, u1.x, u2.x, u3.x);
        *(float4*)(row0 + 4) = make_float4(u4.x, u5.x, u6.x, u7.x);
        *(float4*)(row1)     = make_float4(u0.y, u1.y, u2.y, u3.y);
        *(float4*)(row1 + 4) = make_float4(u4.y, u5.y, u6.y, u7.y);
    }
}

// ============================================================================
extern "C" void kernel_launch(void* const* d_in, const int* in_sizes, int n_in,
                              void* d_out, int out_size)
{
    const float* q = (const float*)d_in[0];
    const float* k = (const float*)d_in[1];
    const float* v = (const float*)d_in[2];
    float* out = (float*)d_out;

    ctx_kernel  <<<dim3(SPLIT, BHN), 128>>>(k, v);
    reduce_kernel<<<BHN, 256>>>();
    out_kernel  <<<dim3(SEQ / ONB, BHN), 128>>>(q, out);
}

// round 6
// speedup vs baseline: 2.0787x; 1.1898x over previous
#include <cuda_runtime.h>

#define BHN   128
#define SEQ   4096
#define DIM   64
#define SPLIT 16
#define RPS   (SEQ / SPLIT)   // 256
#define CHUNK 32
#define EPSF  1e-6f

typedef unsigned long long u64;

// Scratch (device globals: allocation-free per harness rules)
__device__ float g_ctx_partial[BHN * SPLIT * DIM * DIM]; // 33.5 MB
__device__ float g_cs_partial [BHN * SPLIT * DIM];
__device__ float g_ctx        [BHN * DIM * DIM];         // 2 MB natural [d][e]

__device__ __forceinline__ void fma2(u64 &d, u64 a, u64 b) {
    asm("fma.rn.f32x2 %0, %1, %2, %0;" : "+l"(d) : "l"(a), "l"(b));
}
__device__ __forceinline__ float2 unpack2(u64 a) {
    float2 f; asm("mov.b64 {%0, %1}, %2;" : "=f"(f.x), "=f"(f.y) : "l"(a)); return f;
}
// swap halves of a packed f32x2 (2 MOVs)
__device__ __forceinline__ u64 swap2(u64 a) {
    u64 r;
    asm("{\n\t.reg .b32 lo, hi;\n\tmov.b64 {lo,hi}, %1;\n\tmov.b64 %0, {hi,lo};\n\t}"
        : "=l"(r) : "l"(a));
    return r;
}

#define EK_STR 68   // padded row stride (words) -> conflict-free staging stores
#define V_STR  68

// ============================================================================
// Kernel 1: partial ctx[d][e] = sum_n e^{K[n][d]} * V[n][e] over an n-split.
// 128 threads. Per-thread: 4 d x 8 e, BOTH operands natural pairs (diag/anti).
//  warp w, lane l:  dbase = 16w + 4*(l>>3)  (d rows dbase..dbase+3)
//                   eg = l&7 -> e cols {4eg..4eg+3} u {32+4eg..+3}
// Inner per n: 3 LDS.128 (all conflict-free/broadcast) + 2 swap + 16 FFMA2.
// ============================================================================
__global__ __launch_bounds__(128, 6)
void ctx_kernel(const float* __restrict__ kp, const float* __restrict__ vp)
{
    __shared__ __align__(16) float s_ek[CHUNK * EK_STR]; // 8.5 KB natural [n][d]
    __shared__ __align__(16) float s_v [CHUNK * V_STR];  // 8.5 KB natural [n][e]
    __shared__ __align__(16) float s_red[8 * DIM];       // 2 KB

    const int tid = threadIdx.x;
    const int w = tid >> 5, l = tid & 31;
    const int dbase = 16 * w + 4 * (l >> 3);
    const int eg = l & 7;
    const int hh = tid >> 4, dcol = tid & 15;        // staging coords
    const int split = blockIdx.x, bh = blockIdx.y;
    const size_t base = ((size_t)bh * SEQ + (size_t)split * RPS) * DIM;

    u64 accD[2][4], accA[2][4];                      // [d-pair][e-pair] diag/anti
#pragma unroll
    for (int i = 0; i < 2; i++)
#pragma unroll
        for (int j = 0; j < 4; j++) { accD[i][j] = 0ull; accA[i][j] = 0ull; }
    float4 cs = make_float4(0.f, 0.f, 0.f, 0.f);     // colsum for d=4dcol..+3

    for (int ch = 0; ch < RPS / CHUNK; ch++) {
        // ---- stage chunk (natural layouts, padded stride) ----
#pragma unroll
        for (int r = 0; r < 4; r++) {
            const int nl = 8 * r + hh;               // 0..31
            const size_t goff = base + (size_t)(ch * CHUNK + nl) * DIM + 4 * dcol;
            const float4 kk = *(const float4*)(kp + goff);
            const float e0 = __expf(kk.x), e1 = __expf(kk.y),
                        e2 = __expf(kk.z), e3 = __expf(kk.w);
            cs.x += e0; cs.y += e1; cs.z += e2; cs.w += e3;
            *(float4*)&s_ek[nl * EK_STR + 4 * dcol] = make_float4(e0, e1, e2, e3);
            *(float4*)&s_v [nl * V_STR  + 4 * dcol] = *(const float4*)(vp + goff);
        }
        __syncthreads();

        // ---- rank-1 updates ----
#pragma unroll 8
        for (int n = 0; n < CHUNK; n++) {
            const ulonglong2 dd = *(const ulonglong2*)&s_ek[n * EK_STR + dbase]; // (d0,d1),(d2,d3)
            const u64 s0 = swap2(dd.x), s1 = swap2(dd.y);
            const ulonglong2 v0 = *(const ulonglong2*)&s_v[n * V_STR + 4 * eg];      // (e0,e1),(e2,e3)
            const ulonglong2 v1 = *(const ulonglong2*)&s_v[n * V_STR + 32 + 4 * eg]; // (E0,E1),(E2,E3)
            fma2(accD[0][0], dd.x, v0.x); fma2(accA[0][0], s0, v0.x);
            fma2(accD[0][1], dd.x, v0.y); fma2(accA[0][1], s0, v0.y);
            fma2(accD[0][2], dd.x, v1.x); fma2(accA[0][2], s0, v1.x);
            fma2(accD[0][3], dd.x, v1.y); fma2(accA[0][3], s0, v1.y);
            fma2(accD[1][0], dd.y, v0.x); fma2(accA[1][0], s1, v0.x);
            fma2(accD[1][1], dd.y, v0.y); fma2(accA[1][1], s1, v0.y);
            fma2(accD[1][2], dd.y, v1.x); fma2(accA[1][2], s1, v1.x);
            fma2(accD[1][3], dd.y, v1.y); fma2(accA[1][3], s1, v1.y);
        }
        __syncthreads();
    }

    // ---- colsum partial ----
    *(float4*)&s_red[hh * DIM + 4 * dcol] = cs;
    __syncthreads();
    const int pbase = bh * SPLIT + split;
    if (tid < DIM) {
        float s = 0.f;
#pragma unroll
        for (int y = 0; y < 8; y++) s += s_red[y * DIM + tid];
        g_cs_partial[pbase * DIM + tid] = s;
    }

    // ---- context partial (plain [d][e]) ----
    // block (d0,d1)x(e0,e1): row d0 = (D.x, A.y); row d1 = (A.x, D.y)
    float* cp = g_ctx_partial + (size_t)pbase * DIM * DIM;
#pragma unroll
    for (int p = 0; p < 2; p++) {
        const float2 D0 = unpack2(accD[p][0]), A0 = unpack2(accA[p][0]);
        const float2 D1 = unpack2(accD[p][1]), A1 = unpack2(accA[p][1]);
        const float2 D2 = unpack2(accD[p][2]), A2 = unpack2(accA[p][2]);
        const float2 D3 = unpack2(accD[p][3]), A3 = unpack2(accA[p][3]);
        float* r0 = cp + (size_t)(dbase + 2 * p) * DIM;
        float* r1 = r0 + DIM;
        *(float4*)(r0 + 4 * eg)      = make_float4(D0.x, A0.y, D1.x, A1.y);
        *(float4*)(r0 + 32 + 4 * eg) = make_float4(D2.x, A2.y, D3.x, A3.y);
        *(float4*)(r1 + 4 * eg)      = make_float4(A0.x, D0.y, A1.x, D1.y);
        *(float4*)(r1 + 32 + 4 * eg) = make_float4(A2.x, D2.y, A3.x, D3.y);
    }
}

// ============================================================================
// Kernel 2: reduce split partials, normalize, emit NATURAL fp32 context.
// ============================================================================
__global__ __launch_bounds__(256)
void reduce_kernel()
{
    const int bh = blockIdx.x, tid = threadIdx.x;
    __shared__ float inv[DIM];
    if (tid < DIM) {
        float s = 0.f;
#pragma unroll
        for (int sp = 0; sp < SPLIT; sp++)
            s += g_cs_partial[(bh * SPLIT + sp) * DIM + tid];
        inv[tid] = 1.0f / (s * (1.0f + EPSF));
    }
    __syncthreads();
#pragma unroll
    for (int r = 0; r < 4; r++) {
        const int i4 = r * 256 + tid;                // float4 index over [d][e]
        float4 s = make_float4(0.f, 0.f, 0.f, 0.f);
#pragma unroll
        for (int sp = 0; sp < SPLIT; sp++) {
            const float4 p = *(const float4*)(g_ctx_partial +
                (size_t)(bh * SPLIT + sp) * DIM * DIM + 4 * i4);
            s.x += p.x; s.y += p.y; s.z += p.z; s.w += p.w;
        }
        const float iv = inv[i4 >> 4];
        s.x *= iv; s.y *= iv; s.z *= iv; s.w *= iv;
        *(float4*)(g_ctx + (size_t)bh * DIM * DIM + 4 * i4) = s;
    }
}

// ============================================================================
// Kernel 3: out = rowsoftmax(Q) @ ctx.  128 threads, 128 n-rows per block.
// Per-thread: 8 n x 8 e, both operands natural pairs (diag/anti).
//  warp w, lane l:  nbase = 32w + 8*(l>>3) ;  eg = l&7 -> e {4eg..}+{32+4eg..}
// Inner per d: 4 LDS.128 + 4 swap + 32 FFMA2.
// ============================================================================
#define ONB    128
#define PT_STR 128
#define C_STR  68

__global__ __launch_bounds__(128, 4)
void out_kernel(const float* __restrict__ qp, float* __restrict__ outp)
{
    __shared__ __align__(16) float s_pT[DIM * PT_STR]; // 32 KB  p^T [d][n]
    __shared__ __align__(16) float s_c [DIM * C_STR];  // 17 KB  natural ctx [d][e]

    const int tid = threadIdx.x;
    const int w = tid >> 5, l = tid & 31;
    const int nbase = 32 * w + 8 * (l >> 3);
    const int eg = l & 7;
    const int nb = blockIdx.x, bh = blockIdx.y;

    // stage natural ctx (padded stride)
    {
        const float4* src = (const float4*)(g_ctx + (size_t)bh * DIM * DIM);
#pragma unroll
        for (int r = 0; r < 8; r++) {
            const int i = r * 128 + tid;             // 0..1023 float4s, i = d*16+c
            const int d = i >> 4, c = i & 15;
            *(float4*)&s_c[d * C_STR + 4 * c] = src[i];
        }
    }

    // row softmax of q: 2 threads per row, 2 passes of 64 rows
#pragma unroll
    for (int pass = 0; pass < 2; pass++) {
        const int row = 64 * pass + (tid >> 1), part = tid & 1;
        const float* qr = qp + ((size_t)bh * SEQ + (size_t)nb * ONB + row) * DIM + part * 32;
        float e[32];
#pragma unroll
        for (int i = 0; i < 8; i++) {
            const float4 a = *(const float4*)(qr + 4 * i);
            e[4*i] = a.x; e[4*i+1] = a.y; e[4*i+2] = a.z; e[4*i+3] = a.w;
        }
        float m = e[0];
#pragma unroll
        for (int i = 1; i < 32; i++) m = fmaxf(m, e[i]);
        m = fmaxf(m, __shfl_xor_sync(0xffffffffu, m, 1));
        float s = 0.f;
#pragma unroll
        for (int i = 0; i < 32; i++) { e[i] = __expf(e[i] - m); s += e[i]; }
        s += __shfl_xor_sync(0xffffffffu, s, 1);
        const float rinv = 1.0f / s;
#pragma unroll
        for (int i = 0; i < 32; i++)
            s_pT[(32 * part + i) * PT_STR + row] = e[i] * rinv;
    }
    __syncthreads();

    // GEMM: out[n][e] = sum_d p[n][d] * ctx[d][e]
    u64 accD[4][4], accA[4][4];                      // [n-pair][e-pair]
#pragma unroll
    for (int i = 0; i < 4; i++)
#pragma unroll
        for (int j = 0; j < 4; j++) { accD[i][j] = 0ull; accA[i][j] = 0ull; }

#pragma unroll 8
    for (int d = 0; d < DIM; d++) {
        const float* pd = s_pT + d * PT_STR + nbase;
        const ulonglong2 pA = *(const ulonglong2*)(pd);       // (n0,n1),(n2,n3)
        const ulonglong2 pB = *(const ulonglong2*)(pd + 4);   // (n4,n5),(n6,n7)
        const u64 sA0 = swap2(pA.x), sA1 = swap2(pA.y);
        const u64 sB0 = swap2(pB.x), sB1 = swap2(pB.y);
        const float* cd = s_c + d * C_STR;
        const ulonglong2 c0 = *(const ulonglong2*)(cd + 4 * eg);      // (e0,e1),(e2,e3)
        const ulonglong2 c1 = *(const ulonglong2*)(cd + 32 + 4 * eg); // (E0,E1),(E2,E3)
        fma2(accD[0][0], pA.x, c0.x); fma2(accA[0][0], sA0, c0.x);
        fma2(accD[0][1], pA.x, c0.y); fma2(accA[0][1], sA0, c0.y);
        fma2(accD[0][2], pA.x, c1.x); fma2(accA[0][2], sA0, c1.x);
        fma2(accD[0][3], pA.x, c1.y); fma2(accA[0][3], sA0, c1.y);
        fma2(accD[1][0], pA.y, c0.x); fma2(accA[1][0], sA1, c0.x);
        fma2(accD[1][1], pA.y, c0.y); fma2(accA[1][1], sA1, c0.y);
        fma2(accD[1][2], pA.y, c1.x); fma2(accA[1][2], sA1, c1.x);
        fma2(accD[1][3], pA.y, c1.y); fma2(accA[1][3], sA1, c1.y);
        fma2(accD[2][0], pB.x, c0.x); fma2(accA[2][0], sB0, c0.x);
        fma2(accD[2][1], pB.x, c0.y); fma2(accA[2][1], sB0, c0.y);
        fma2(accD[2][2], pB.x, c1.x); fma2(accA[2][2], sB0, c1.x);
        fma2(accD[2][3], pB.x, c1.y); fma2(accA[2][3], sB0, c1.y);
        fma2(accD[3][0], pB.y, c0.x); fma2(accA[3][0], sB1, c0.x);
        fma2(accD[3][1], pB.y, c0.y); fma2(accA[3][1], sB1, c0.y);
        fma2(accD[3][2], pB.y, c1.x); fma2(accA[3][2], sB1, c1.x);
        fma2(accD[3][3], pB.y, c1.y); fma2(accA[3][3], sB1, c1.y);
    }

    // epilogue: block (n0,n1)x(e0,e1): row n0 = (D.x, A.y); row n1 = (A.x, D.y)
    const size_t obase = ((size_t)bh * SEQ + (size_t)nb * ONB) * DIM;
#pragma unroll
    for (int p = 0; p < 4; p++) {
        const float2 D0 = unpack2(accD[p][0]), A0 = unpack2(accA[p][0]);
        const float2 D1 = unpack2(accD[p][1]), A1 = unpack2(accA[p][1]);
        const float2 D2 = unpack2(accD[p][2]), A2 = unpack2(accA[p][2]);
        const float2 D3 = unpack2(accD[p][3]), A3 = unpack2(accA[p][3]);
        float* r0 = outp + obase + (size_t)(nbase + 2 * p) * DIM;
        float* r1 = r0 + DIM;
        *(float4*)(r0 + 4 * eg)      = make_float4(D0.x, A0.y, D1.x, A1.y);
        *(float4*)(r0 + 32 + 4 * eg) = make_float4(D2.x, A2.y, D3.x, A3.y);
        *(float4*)(r1 + 4 * eg)      = make_float4(A0.x, D0.y, A1.x, D1.y);
        *(float4*)(r1 + 32 + 4 * eg) = make_float4(A2.x, D2.y, A3.x, D3.y);
    }
}

// ============================================================================
extern "C" void kernel_launch(void* const* d_in, const int* in_sizes, int n_in,
                              void* d_out, int out_size)
{
    const float* q = (const float*)d_in[0];
    const float* k = (const float*)d_in[1];
    const float* v = (const float*)d_in[2];
    float* out = (float*)d_out;

    ctx_kernel  <<<dim3(SPLIT, BHN), 128>>>(k, v);
    reduce_kernel<<<BHN, 256>>>();
    out_kernel  <<<dim3(SEQ / ONB, BHN), 128>>>(q, out);
}